// round 8
// baseline (speedup 1.0000x reference)
#include <cuda_runtime.h>
#include <cuda_bf16.h>

// Problem constants (match reference)
#define B_SZ       128
#define S_SZ       4096
#define TOK        64          // token_dim
#define EFF        60          // token_dim - 4
#define NF         20          // num features
#define H0         256
#define H1         128
#define H2         64
#define OUT        3
#define CHUNKS     4           // seq chunks per batch
#define CHUNK_S    (S_SZ / CHUNKS)   // 1024 tokens per chunk
#define NT_MLP     512

// Scratch: partial column sums per (batch, chunk): [B, CHUNKS, TOK]
__device__ float g_partial[B_SZ * CHUNKS * TOK];

__device__ __forceinline__ void l2_prefetch(const void* p) {
    asm volatile("prefetch.global.L2 [%0];" :: "l"(p));
}

// ---------------------------------------------------------------------------
// Kernel 1: streaming column-sum (R1 geometry: 512 blocks x 256 threads —
// measured ~6.8 TB/s). Also prefetches MLP weights into L2 (2 lines/block
// covers w1+w2+w0+w_ext fully across the 512 blocks).
// ---------------------------------------------------------------------------
__global__ __launch_bounds__(256, 8)
void mean_sum_kernel(const float* __restrict__ x,
                     const float* __restrict__ w_ext,
                     const float* __restrict__ w0,
                     const float* __restrict__ w1,
                     const float* __restrict__ w2) {
    const int b = blockIdx.x >> 2;        // batch
    const int c = blockIdx.x & 3;         // chunk
    const int t = threadIdx.x;            // 0..255
    const int blk = blockIdx.x;           // 0..511

    // Weight prefetch: w1 = 1024 lines (2/block), w2 = 256 lines (blk<256),
    // w0 = 160 lines (blk<160), w_ext = 38 lines (blk<38).
    if (t == 0)       l2_prefetch(w1 + (blk * 2 + 0) * 32);
    else if (t == 1)  l2_prefetch(w1 + (blk * 2 + 1) * 32);
    else if (t == 2 && blk < 256) l2_prefetch(w2 + blk * 32);
    else if (t == 3 && blk < 160) l2_prefetch(w0 + blk * 32);
    else if (t == 4 && blk < 38)  l2_prefetch(w_ext + blk * 32);

    const float4* __restrict__ p =
        (const float4*)(x + ((size_t)b * S_SZ + (size_t)c * CHUNK_S) * TOK);

    // CHUNK_S * TOK / 4 = 16384 float4 per block; 64 per thread.
    float4 acc = make_float4(0.f, 0.f, 0.f, 0.f);
    #pragma unroll 16
    for (int i = t; i < CHUNK_S * (TOK / 4); i += 256) {
        float4 v = __ldcs(&p[i]);         // streaming: x touched once
        acc.x += v.x; acc.y += v.y; acc.z += v.z; acc.w += v.w;
    }

    __shared__ float4 sm[256];
    sm[t] = acc;
    __syncthreads();

    // 16 column groups (t % 16 fixed by stride 256 = 16*16).
    if (t < 16) {
        float4 s = make_float4(0.f, 0.f, 0.f, 0.f);
        #pragma unroll
        for (int k = 0; k < 16; k++) {
            float4 v = sm[t + k * 16];
            s.x += v.x; s.y += v.y; s.z += v.z; s.w += v.w;
        }
        float* dst = &g_partial[(size_t)(b * CHUNKS + c) * TOK + t * 4];
        dst[0] = s.x; dst[1] = s.y; dst[2] = s.z; dst[3] = s.w;
    }
}

// ---------------------------------------------------------------------------
// Kernel 2: per-batch MLP with warp-per-neuron coalesced weight reads
// (R6 phase-2 structure). grid = 128 blocks x 512 threads; weights L2-warm.
// ---------------------------------------------------------------------------
__global__ __launch_bounds__(NT_MLP, 2)
void mlp_kernel(const float* __restrict__ w_ext, const float* __restrict__ b_ext,
                const float* __restrict__ w0, const float* __restrict__ b0,
                const float* __restrict__ w1, const float* __restrict__ b1,
                const float* __restrict__ w2, const float* __restrict__ b2,
                const float* __restrict__ w3, const float* __restrict__ b3,
                float* __restrict__ out) {
    const int b = blockIdx.x;
    const int t = threadIdx.x;
    const int w = t >> 5;                 // warp 0..15
    const int lane = t & 31;

    __shared__ float xm[TOK];
    __shared__ float feats[NF];
    __shared__ float a0[H0];
    __shared__ float a1[H1];
    __shared__ float a2[H2];

    // Combine chunk partials -> mean
    if (t < TOK) {
        const float* p0 = &g_partial[(size_t)(b * CHUNKS) * TOK + t];
        float s = (p0[0] + p0[TOK]) + (p0[2 * TOK] + p0[3 * TOK]);
        xm[t] = s * (1.0f / (float)S_SZ);
    }
    __syncthreads();

    // Extractor: 20 neurons, 60-dot. Warp w does neuron w (and 16+w for w<4).
    {
        #pragma unroll
        for (int r = 0; r < 2; r++) {
            const int j = w + r * 16;
            if (j < NF) {
                float s = 0.f;
                if (lane < 15) {
                    const float4 wv = ((const float4*)(w_ext + j * EFF))[lane];
                    const float4 av = ((const float4*)xm)[lane];
                    s = fmaf(av.x, wv.x, fmaf(av.y, wv.y,
                        fmaf(av.z, wv.z, av.w * wv.w)));
                }
                s += __shfl_xor_sync(0xFFFFFFFF, s, 1);
                s += __shfl_xor_sync(0xFFFFFFFF, s, 2);
                s += __shfl_xor_sync(0xFFFFFFFF, s, 4);
                s += __shfl_xor_sync(0xFFFFFFFF, s, 8);
                s += __shfl_xor_sync(0xFFFFFFFF, s, 16);
                if (lane == 0) feats[j] = s + b_ext[j];
            }
        }
    }
    __syncthreads();

    // Layer 0: 20 -> 256 + ReLU. One neuron per thread (t < 256).
    if (t < H0) {
        const float* __restrict__ wp = w0 + t * NF;
        float s0 = b0[t], s1 = 0.f;
        #pragma unroll
        for (int k = 0; k < NF; k += 2) {
            s0 = fmaf(feats[k + 0], wp[k + 0], s0);
            s1 = fmaf(feats[k + 1], wp[k + 1], s1);
        }
        a0[t] = fmaxf(s0 + s1, 0.f);
    }
    __syncthreads();

    // Layer 1: 256 -> 128 + ReLU. Warp w does neurons j = w + 16r, r=0..7.
    // Lane reads float4 #lane and #(lane+32) of the 1KB row -> coalesced.
    {
        #pragma unroll
        for (int r = 0; r < 8; r++) {
            const int j = w + r * 16;
            const float4* __restrict__ wr = (const float4*)(w1 + j * H0);
            const float4* __restrict__ ar = (const float4*)a0;
            float4 w0v = wr[lane];
            float4 w1v = wr[lane + 32];
            float4 a0v = ar[lane];
            float4 a1v = ar[lane + 32];
            float s0 = fmaf(a0v.x, w0v.x, a0v.y * w0v.y);
            float s1 = fmaf(a0v.z, w0v.z, a0v.w * w0v.w);
            float s2 = fmaf(a1v.x, w1v.x, a1v.y * w1v.y);
            float s3 = fmaf(a1v.z, w1v.z, a1v.w * w1v.w);
            float s = (s0 + s1) + (s2 + s3);
            s += __shfl_xor_sync(0xFFFFFFFF, s, 1);
            s += __shfl_xor_sync(0xFFFFFFFF, s, 2);
            s += __shfl_xor_sync(0xFFFFFFFF, s, 4);
            s += __shfl_xor_sync(0xFFFFFFFF, s, 8);
            s += __shfl_xor_sync(0xFFFFFFFF, s, 16);
            if (lane == 0) a1[j] = fmaxf(s + b1[j], 0.f);
        }
    }
    __syncthreads();

    // Layer 2: 128 -> 64 + ReLU. Warp w does neurons j = w + 16r, r=0..3.
    {
        #pragma unroll
        for (int r = 0; r < 4; r++) {
            const int j = w + r * 16;
            const float4 wv = ((const float4*)(w2 + j * H1))[lane];
            const float4 av = ((const float4*)a1)[lane];
            float s = fmaf(av.x, wv.x, fmaf(av.y, wv.y,
                      fmaf(av.z, wv.z, av.w * wv.w)));
            s += __shfl_xor_sync(0xFFFFFFFF, s, 1);
            s += __shfl_xor_sync(0xFFFFFFFF, s, 2);
            s += __shfl_xor_sync(0xFFFFFFFF, s, 4);
            s += __shfl_xor_sync(0xFFFFFFFF, s, 8);
            s += __shfl_xor_sync(0xFFFFFFFF, s, 16);
            if (lane == 0) a2[j] = fmaxf(s + b2[j], 0.f);
        }
    }
    __syncthreads();

    // Layer 3: 64 -> 3. Warps 0..2, one neuron each; lanes 0..15 read float4.
    if (w < OUT) {
        const int j = w;
        float s = 0.f;
        if (lane < 16) {
            const float4 wv = ((const float4*)(w3 + j * H2))[lane];
            const float4 av = ((const float4*)a2)[lane];
            s = fmaf(av.x, wv.x, fmaf(av.y, wv.y,
                fmaf(av.z, wv.z, av.w * wv.w)));
        }
        s += __shfl_xor_sync(0xFFFFFFFF, s, 1);
        s += __shfl_xor_sync(0xFFFFFFFF, s, 2);
        s += __shfl_xor_sync(0xFFFFFFFF, s, 4);
        s += __shfl_xor_sync(0xFFFFFFFF, s, 8);
        s += __shfl_xor_sync(0xFFFFFFFF, s, 16);
        if (lane == 0) out[b * OUT + j] = s + b3[j];
    }
}

extern "C" void kernel_launch(void* const* d_in, const int* in_sizes, int n_in,
                              void* d_out, int out_size) {
    const float* x     = (const float*)d_in[0];
    const float* w_ext = (const float*)d_in[1];
    const float* b_ext = (const float*)d_in[2];
    const float* w0    = (const float*)d_in[3];
    const float* b0    = (const float*)d_in[4];
    const float* w1    = (const float*)d_in[5];
    const float* b1    = (const float*)d_in[6];
    const float* w2    = (const float*)d_in[7];
    const float* b2    = (const float*)d_in[8];
    const float* w3    = (const float*)d_in[9];
    const float* b3    = (const float*)d_in[10];
    float* out = (float*)d_out;

    mean_sum_kernel<<<B_SZ * CHUNKS, 256>>>(x, w_ext, w0, w1, w2);
    mlp_kernel<<<B_SZ, NT_MLP>>>(w_ext, b_ext, w0, b0, w1, b1,
                                 w2, b2, w3, b3, out);
}